// round 13
// baseline (speedup 1.0000x reference)
#include <cuda_runtime.h>
#include <cuda_fp16.h>
#include <math.h>
#include <stdint.h>

#define SEQ   4096
#define HDIM  4096
#define INNER 4096
#define NH    32
#define HD    128
#define BLK   256
#define NB    16
#define QKVW  12288
#define EPS_RMS 1e-5f

#define GK    4096
#define BM    128
#define BN    128
#define BK    64
#define NTHR  128
#define KTILES (GK / BK)    // 64
#define KPADH 72
#define STGH_A (128 * KPADH)
#define STAGE_BYTES (2 * STGH_A * 2)    // 36864
#define NSTG  3
#define GEMM_SMEM (NSTG * STAGE_BYTES)  // 110592 -> 2 CTAs/SM

#define KP2   136
#define PSTR  72
#define ATTNOUT_SMEM (3 * 256 * KP2 * 2 + 8 * 16 * PSTR * 2)   // 227328

#define RASTW 8   // L2 raster: n-tile chunk width (m fastest within chunk)

// ---------------- scratch ----------------
__device__ __half g_qkvh[(size_t)SEQ * QKVW];
__device__ float  g_hidden[(size_t)SEQ * INNER];
__device__ __half g_gateh[(size_t)SEQ * INNER];
__device__ float  g_S[(size_t)NH * NB * HD * HD];
__device__ __half g_kvsth[(size_t)NH * NB * HD * HD];
__device__ __half g_xh[(size_t)SEQ * HDIM];
__device__ __half g_wqkvh[(size_t)QKVW * HDIM];
__device__ __half g_wgateh[(size_t)INNER * HDIM];
__device__ __half g_wouth[(size_t)HDIM * INNER];
__device__ __half g_ghalf[(size_t)SEQ * INNER];

// ---------------- helpers ----------------
__device__ __forceinline__ uint32_t smem_u32(const void* p) {
    uint32_t a;
    asm("{ .reg .u64 t; cvta.to.shared.u64 t, %1; cvt.u32.u64 %0, t; }" : "=r"(a) : "l"(p));
    return a;
}

__device__ __forceinline__ void cp_async16(uint32_t dst, const void* src) {
    asm volatile("cp.async.cg.shared.global [%0], [%1], 16;" :: "r"(dst), "l"(src));
}
#define CP_COMMIT() asm volatile("cp.async.commit_group;" ::: "memory")
#define CP_WAIT(n)  asm volatile("cp.async.wait_group %0;" :: "n"(n) : "memory")

__device__ __forceinline__ void ldsm_x4(uint32_t& r0, uint32_t& r1, uint32_t& r2, uint32_t& r3,
                                        uint32_t addr) {
    asm volatile("ldmatrix.sync.aligned.m8n8.x4.shared.b16 {%0,%1,%2,%3}, [%4];"
        : "=r"(r0), "=r"(r1), "=r"(r2), "=r"(r3) : "r"(addr));
}
__device__ __forceinline__ void ldsm_x4_t(uint32_t& r0, uint32_t& r1, uint32_t& r2, uint32_t& r3,
                                          uint32_t addr) {
    asm volatile("ldmatrix.sync.aligned.m8n8.x4.trans.shared.b16 {%0,%1,%2,%3}, [%4];"
        : "=r"(r0), "=r"(r1), "=r"(r2), "=r"(r3) : "r"(addr));
}

__device__ __forceinline__ void mma_f16(float* c, const uint32_t* a, const uint32_t* b) {
    asm volatile(
        "mma.sync.aligned.m16n8k16.row.col.f32.f16.f16.f32 "
        "{%0,%1,%2,%3}, {%4,%5,%6,%7}, {%8,%9}, {%0,%1,%2,%3};"
        : "+f"(c[0]), "+f"(c[1]), "+f"(c[2]), "+f"(c[3])
        : "r"(a[0]), "r"(a[1]), "r"(a[2]), "r"(a[3]), "r"(b[0]), "r"(b[1]));
}

__device__ __forceinline__ float silu_f(float v)  { return v / (1.0f + expf(-v)); }
__device__ __forceinline__ float sigm_f(float v)  { return 1.0f / (1.0f + expf(-v)); }

// ---------------- fused fp32 -> fp16 conversion ----------------
#define N1 (SEQ * HDIM / 8)
#define N2 (QKVW * HDIM / 8)
#define N3 (INNER * HDIM / 8)
#define N4 (HDIM * INNER / 8)
__global__ __launch_bounds__(256)
void cvt_all_kernel(const float* __restrict__ x,  const float* __restrict__ wq,
                    const float* __restrict__ wg, const float* __restrict__ wo,
                    __half* __restrict__ xh,  __half* __restrict__ wqh,
                    __half* __restrict__ wgh, __half* __restrict__ woh)
{
    int i = blockIdx.x * 256 + threadIdx.x;
    const float* in; __half* out; int j;
    if (i < N1)                { in = x;  out = xh;  j = i; }
    else if (i < N1 + N2)      { in = wq; out = wqh; j = i - N1; }
    else if (i < N1 + N2 + N3) { in = wg; out = wgh; j = i - N1 - N2; }
    else                       { in = wo; out = woh; j = i - N1 - N2 - N3; }
    float4 v0 = ((const float4*)in)[j * 2];
    float4 v1 = ((const float4*)in)[j * 2 + 1];
    __half2 h0 = __floats2half2_rn(v0.x, v0.y);
    __half2 h1 = __floats2half2_rn(v0.z, v0.w);
    __half2 h2 = __floats2half2_rn(v1.x, v1.y);
    __half2 h3 = __floats2half2_rn(v1.z, v1.w);
    uint4 o;
    o.x = *(uint32_t*)&h0; o.y = *(uint32_t*)&h1;
    o.z = *(uint32_t*)&h2; o.w = *(uint32_t*)&h3;
    ((uint4*)out)[j] = o;
}

// ---------------- GEMM mainloop (round-11 committed) ----------------
__device__ __forceinline__ void g_load_stage(uint32_t sbase, int slot, int s,
                                             const __half* __restrict__ Ab,
                                             const __half* __restrict__ Bb, int t)
{
    const uint32_t stA = sbase + slot * STAGE_BYTES;
    const uint32_t stB = stA + STGH_A * 2;
    const __half* ga = Ab + (size_t)s * BK;
    const __half* gb = Bb + (size_t)s * BK;
#pragma unroll
    for (int i = 0; i < 8; ++i) {
        int id = t + NTHR * i;
        int row = id >> 3, c = id & 7;
        cp_async16(stA + (row * KPADH + c * 8) * 2, ga + (size_t)row * GK + c * 8);
    }
#pragma unroll
    for (int i = 0; i < 8; ++i) {
        int id = t + NTHR * i;
        int row = id >> 3, c = id & 7;
        cp_async16(stB + (row * KPADH + c * 8) * 2, gb + (size_t)row * GK + c * 8);
    }
}

__device__ __forceinline__ void lds_frags(uint32_t sA, uint32_t sB, int k0,
                                          int wm, int wn, int r, int q,
                                          uint32_t af[4][4], uint32_t bf[8][2])
{
#pragma unroll
    for (int i = 0; i < 4; ++i) {
        uint32_t ap = sA + ((wm + i * 16 + r) * KPADH + k0 + 2 * q) * 2;
        asm volatile("ld.shared.b32 %0, [%1];" : "=r"(af[i][0]) : "r"(ap));
        asm volatile("ld.shared.b32 %0, [%1];" : "=r"(af[i][1]) : "r"(ap + 8 * KPADH * 2));
        asm volatile("ld.shared.b32 %0, [%1];" : "=r"(af[i][2]) : "r"(ap + 16));
        asm volatile("ld.shared.b32 %0, [%1];" : "=r"(af[i][3]) : "r"(ap + 8 * KPADH * 2 + 16));
    }
#pragma unroll
    for (int j = 0; j < 8; ++j) {
        uint32_t bp = sB + ((wn + j * 8 + r) * KPADH + k0 + 2 * q) * 2;
        asm volatile("ld.shared.b32 %0, [%1];" : "=r"(bf[j][0]) : "r"(bp));
        asm volatile("ld.shared.b32 %0, [%1];" : "=r"(bf[j][1]) : "r"(bp + 16));
    }
}

__device__ __forceinline__ void gemm_mainloop(uint32_t sbase, const __half* Ab,
                                              const __half* Bb, int t, int wm, int wn,
                                              int r, int q, float c[4][8][4])
{
#pragma unroll
    for (int i = 0; i < 4; ++i)
#pragma unroll
        for (int j = 0; j < 8; ++j)
#pragma unroll
            for (int p = 0; p < 4; ++p) c[i][j][p] = 0.0f;

    g_load_stage(sbase, 0, 0, Ab, Bb, t); CP_COMMIT();
    g_load_stage(sbase, 1, 1, Ab, Bb, t); CP_COMMIT();

    for (int s = 0; s < KTILES; ++s) {
        const int slot = s % NSTG;
        CP_WAIT(1);
        __syncthreads();

        if (s + 2 < KTILES) {
            g_load_stage(sbase, (s + 2) % NSTG, s + 2, Ab, Bb, t);
        }
        CP_COMMIT();

        const uint32_t sA = sbase + slot * STAGE_BYTES;
        const uint32_t sB = sA + STGH_A * 2;

        uint32_t af[2][4][4], bf[2][8][2];
        lds_frags(sA, sB, 0, wm, wn, r, q, af[0], bf[0]);
#pragma unroll
        for (int ks = 0; ks < 4; ++ks) {
            if (ks < 3)
                lds_frags(sA, sB, (ks + 1) * 16, wm, wn, r, q,
                          af[(ks + 1) & 1], bf[(ks + 1) & 1]);
#pragma unroll
            for (int i = 0; i < 4; ++i)
#pragma unroll
                for (int j = 0; j < 8; ++j)
                    mma_f16(c[i][j], af[ks & 1][i], bf[ks & 1][j]);
        }
    }
}

// L2-aware raster: m fastest within chunks of RASTW n-tiles.
__device__ __forceinline__ void raster_map(int& m_t, int& n_t) {
    const int bid = blockIdx.y * gridDim.x + blockIdx.x;
    const int mt  = gridDim.y;
    const int per_chunk = mt * RASTW;
    const int chunk = bid / per_chunk;
    const int rem   = bid % per_chunk;
    m_t = rem % mt;
    n_t = chunk * RASTW + rem / mt;
}

// ---------------- fused GEMM1+GEMM2 ----------------
__global__ __launch_bounds__(NTHR, 2)
void gemm_qkvgate(const __half* __restrict__ A,
                  const __half* __restrict__ Bq, const __half* __restrict__ Bg)
{
    extern __shared__ __align__(128) __half smem[];
    const uint32_t sbase = smem_u32(smem);
    const int t    = threadIdx.x;
    const int wid  = t >> 5;
    const int lane = t & 31;

    int m_t, n_t;
    raster_map(m_t, n_t);
    const int bm = m_t * BM;
    const int bn = n_t * BN;

    const bool is_q = (bn < QKVW);
    const int  cbase = is_q ? bn : (bn - QKVW);
    const __half* Bb = (is_q ? Bq : Bg) + (size_t)cbase * GK;
    __half* Ch = (is_q ? g_qkvh : g_gateh);
    const int Ntot = is_q ? QKVW : INNER;
    const __half* Ab = A + (size_t)bm * GK;

    const int wm = (wid & 1) * 64;
    const int wn = (wid >> 1) * 64;
    const int r  = lane >> 2;
    const int q  = lane & 3;

    float c[4][8][4];
    gemm_mainloop(sbase, Ab, Bb, t, wm, wn, r, q, c);

#pragma unroll
    for (int i = 0; i < 4; ++i) {
        const int row0 = bm + wm + i * 16 + r;
#pragma unroll
        for (int j = 0; j < 8; ++j) {
            const int col = cbase + wn + j * 8 + 2 * q;
            float f0, f1, f2, f3;
            if (is_q) {
                f0 = silu_f(c[i][j][0]); f1 = silu_f(c[i][j][1]);
                f2 = silu_f(c[i][j][2]); f3 = silu_f(c[i][j][3]);
            } else {
                f0 = sigm_f(c[i][j][0]); f1 = sigm_f(c[i][j][1]);
                f2 = sigm_f(c[i][j][2]); f3 = sigm_f(c[i][j][3]);
            }
            __half2 h0 = __floats2half2_rn(f0, f1);
            __half2 h1 = __floats2half2_rn(f2, f3);
            *(__half2*)(Ch + (size_t)row0 * Ntot + col)       = h0;
            *(__half2*)(Ch + (size_t)(row0 + 8) * Ntot + col) = h1;
        }
    }
}

// ---------------- GEMM3 ----------------
__global__ __launch_bounds__(NTHR, 2)
void gemm_out(const __half* __restrict__ A, const __half* __restrict__ B,
              float* __restrict__ C)
{
    extern __shared__ __align__(128) __half smem[];
    const uint32_t sbase = smem_u32(smem);
    const int t    = threadIdx.x;
    const int wid  = t >> 5;
    const int lane = t & 31;

    int m_t, n_t;
    raster_map(m_t, n_t);
    const int bm = m_t * BM;
    const int bn = n_t * BN;

    const __half* Ab = A + (size_t)bm * GK;
    const __half* Bb = B + (size_t)bn * GK;

    const int wm = (wid & 1) * 64;
    const int wn = (wid >> 1) * 64;
    const int r  = lane >> 2;
    const int q  = lane & 3;

    float c[4][8][4];
    gemm_mainloop(sbase, Ab, Bb, t, wm, wn, r, q, c);

#pragma unroll
    for (int i = 0; i < 4; ++i) {
        const int row0 = bm + wm + i * 16 + r;
#pragma unroll
        for (int j = 0; j < 8; ++j) {
            const int col = bn + wn + j * 8 + 2 * q;
            *(float2*)(C + (size_t)row0 * HDIM + col)       = make_float2(c[i][j][0], c[i][j][1]);
            *(float2*)(C + (size_t)(row0 + 8) * HDIM + col) = make_float2(c[i][j][2], c[i][j][3]);
        }
    }
}

// ---------------- attention stage A (fp16 mma) ----------------
__global__ __launch_bounds__(128)
void attn_kvblocks_mma(const float* __restrict__ slope)
{
    const int b = blockIdx.x;
    const int h = blockIdx.y;
    const float s = slope[h];

    __shared__ __half Ks[64][KP2];
    __shared__ __half Vs[64][KP2];

    const int t = threadIdx.x;
    const int w = t >> 5, lane = t & 31;
    const int wm = w * 32;
    const int r = lane >> 2, q = lane & 3;
    const int trow = (lane & 7) + ((lane >> 4) & 1) * 8;
    const int tcol = ((lane >> 3) & 1) * 8;

    const __half* kbase = g_qkvh + (size_t)(b * BLK) * QKVW + h * 384 + 128;
    const __half* vbase = kbase + 128;

    const uint32_t sK = smem_u32(Ks);
    const uint32_t sV = smem_u32(Vs);

    float c[2][16][4];
#pragma unroll
    for (int i = 0; i < 2; ++i)
#pragma unroll
        for (int j = 0; j < 16; ++j)
#pragma unroll
            for (int p = 0; p < 4; ++p) c[i][j][p] = 0.0f;

    for (int ch = 0; ch < 4; ++ch) {
        __syncthreads();
#pragma unroll
        for (int it = 0; it < 8; ++it) {
            int id = t + 128 * it;
            int row = id >> 4;
            int c16 = id & 15;
            int i = ch * 64 + row;
            float kd = expf(-s * (float)(255 - i));
            uint4 k4 = *(const uint4*)(kbase + (size_t)i * QKVW + c16 * 8);
            __half2* hp = (__half2*)&k4;
#pragma unroll
            for (int z = 0; z < 4; ++z) {
                float2 f = __half22float2(hp[z]);
                hp[z] = __floats2half2_rn(f.x * kd, f.y * kd);
            }
            *(uint4*)&Ks[row][c16 * 8] = k4;
            uint4 v4 = *(const uint4*)(vbase + (size_t)i * QKVW + c16 * 8);
            *(uint4*)&Vs[row][c16 * 8] = v4;
        }
        __syncthreads();

#pragma unroll
        for (int kc = 0; kc < 4; ++kc) {
            uint32_t af[2][4], bf[16][2];
#pragma unroll
            for (int i16 = 0; i16 < 2; ++i16) {
                uint32_t addr = sK + ((kc * 16 + trow) * KP2 + wm + i16 * 16 + tcol) * 2;
                ldsm_x4_t(af[i16][0], af[i16][1], af[i16][2], af[i16][3], addr);
            }
#pragma unroll
            for (int jj = 0; jj < 8; ++jj) {
                uint32_t addr = sV + ((kc * 16 + trow) * KP2 + jj * 16 + tcol) * 2;
                ldsm_x4_t(bf[2 * jj][0], bf[2 * jj + 1][0], bf[2 * jj][1], bf[2 * jj + 1][1], addr);
            }
#pragma unroll
            for (int i16 = 0; i16 < 2; ++i16)
#pragma unroll
                for (int j = 0; j < 16; ++j)
                    mma_f16(c[i16][j], af[i16], bf[j]);
        }
    }

    float* Sp = g_S + (size_t)(h * NB + b) * HD * HD;
#pragma unroll
    for (int i16 = 0; i16 < 2; ++i16) {
        const int d0 = wm + i16 * 16 + r;
#pragma unroll
        for (int j = 0; j < 16; ++j) {
            const int e = j * 8 + 2 * q;
            *(float2*)(Sp + (size_t)d0 * HD + e)       = make_float2(c[i16][j][0], c[i16][j][1]);
            *(float2*)(Sp + (size_t)(d0 + 8) * HD + e) = make_float2(c[i16][j][2], c[i16][j][3]);
        }
    }
}

// ---------------- attention stage B (fp32 scan, MLP prefetch, fp16 out) ----------------
__global__ void attn_scan(const float* __restrict__ kv_cache, const float* __restrict__ slope)
{
    const int g = blockIdx.x * 256 + threadIdx.x;
    const int h = g >> 14;
    const int e = g & 16383;
    const float dec = expf(-slope[h] * 256.0f);
    const size_t base = (size_t)h * NB * 16384 + e;

    float sv[NB];
#pragma unroll
    for (int b = 0; b < NB; ++b)
        sv[b] = g_S[base + (size_t)b * 16384];

    float c = kv_cache[(size_t)h * 16384 + e];
#pragma unroll
    for (int b = 0; b < NB; ++b) {
        g_kvsth[base + (size_t)b * 16384] = __float2half_rn(c);
        c = dec * c + sv[b];
    }
}

// ---------------- fused attention output ----------------
__global__ __launch_bounds__(256, 1)
void attn_out_mma(const float* __restrict__ slope)
{
    extern __shared__ __align__(128) __half osm[];
    const uint32_t sQ = smem_u32(osm);
    const uint32_t sK = sQ + 256 * KP2 * 2;
    const uint32_t sV = sK + 256 * KP2 * 2;
    const uint32_t sP = sV + 256 * KP2 * 2;

    const int b = blockIdx.x;
    const int h = blockIdx.y;
    const float s = slope[h];

    const int t = threadIdx.x;
    const int w = t >> 5, lane = t & 31;
    const int r = lane >> 2, q = lane & 3;
    const int lrow = (lane & 7) + ((lane >> 3) & 1) * 8;
    const int lcol = (lane >> 4) * 8;
    const int trow = (lane & 7) + ((lane >> 4) & 1) * 8;
    const int tcol = ((lane >> 3) & 1) * 8;

    const __half* qkv = g_qkvh + (size_t)(b * BLK) * QKVW + h * 384;
    const __half* kvst = g_kvsth + (size_t)(h * NB + b) * HD * HD;

    __half* Qs = (__half*)osm;
    __half* KVs = Qs + 256 * KP2;

#pragma unroll
    for (int it = 0; it < 16; ++it) {
        int id = t + 256 * it;
        int row = id >> 4, c16 = id & 15;
        *(uint4*)&Qs[row * KP2 + c16 * 8] = *(const uint4*)(qkv + (size_t)row * QKVW + c16 * 8);
    }
#pragma unroll
    for (int it = 0; it < 8; ++it) {
        int id = t + 256 * it;
        int row = id >> 4, c16 = id & 15;
        *(uint4*)&KVs[row * KP2 + c16 * 8] = *(const uint4*)(kvst + (size_t)row * HD + c16 * 8);
    }
    __syncthreads();

    float oc[2][16][4];
#pragma unroll
    for (int tt = 0; tt < 2; ++tt) {
        const int mt = (tt == 0) ? w : (15 - w);
#pragma unroll
        for (int j = 0; j < 16; ++j)
#pragma unroll
            for (int p = 0; p < 4; ++p) oc[tt][j][p] = 0.0f;

#pragma unroll
        for (int kc = 0; kc < 8; ++kc) {
            uint32_t qa[4], bf[16][2];
            ldsm_x4(qa[0], qa[1], qa[2], qa[3],
                    sQ + ((mt * 16 + lrow) * KP2 + kc * 16 + lcol) * 2);
#pragma unroll
            for (int jj = 0; jj < 8; ++jj) {
                ldsm_x4_t(bf[2 * jj][0], bf[2 * jj + 1][0],
                          bf[2 * jj][1], bf[2 * jj + 1][1],
                          sK + ((kc * 16 + trow) * KP2 + jj * 16 + tcol) * 2);
            }
#pragma unroll
            for (int j = 0; j < 16; ++j) mma_f16(oc[tt][j], qa, bf[j]);
        }

        const int mrow = mt * 16 + r;
        const float qd0 = expf(-s * (float)(mrow + 1));
        const float qd8 = expf(-s * (float)(mrow + 9));
#pragma unroll
        for (int j = 0; j < 16; ++j) {
            oc[tt][j][0] *= qd0; oc[tt][j][1] *= qd0;
            oc[tt][j][2] *= qd8; oc[tt][j][3] *= qd8;
        }
    }
    __syncthreads();

    __half* Ks = KVs;
    __half* Vs = Ks + 256 * KP2;
#pragma unroll
    for (int it = 0; it < 16; ++it) {
        int id = t + 256 * it;
        int row = id >> 4, c16 = id & 15;
        *(uint4*)&Ks[row * KP2 + c16 * 8] = *(const uint4*)(qkv + 128 + (size_t)row * QKVW + c16 * 8);
        *(uint4*)&Vs[row * KP2 + c16 * 8] = *(const uint4*)(qkv + 256 + (size_t)row * QKVW + c16 * 8);
    }
    __syncthreads();

    const uint32_t sPw = sP + w * 16 * PSTR * 2;
    __half* Pw = (__half*)(osm) + (sPw - sQ) / 2;

#pragma unroll
    for (int tt = 0; tt < 2; ++tt) {
        const int mt = (tt == 0) ? w : (15 - w);
        const int mrow = mt * 16 + r;

        const int nchunks = mt / 4 + 1;
        for (int nt = 0; nt < nchunks; ++nt) {
            float pc[8][4];
#pragma unroll
            for (int j = 0; j < 8; ++j)
#pragma unroll
                for (int p = 0; p < 4; ++p) pc[j][p] = 0.0f;

#pragma unroll
            for (int kc = 0; kc < 8; ++kc) {
                uint32_t qa[4], kb[8][2];
                ldsm_x4(qa[0], qa[1], qa[2], qa[3],
                        sQ + ((mt * 16 + lrow) * KP2 + kc * 16 + lcol) * 2);
#pragma unroll
                for (int j16 = 0; j16 < 4; ++j16) {
                    ldsm_x4(kb[2 * j16][0], kb[2 * j16 + 1][0],
                            kb[2 * j16][1], kb[2 * j16 + 1][1],
                            sK + ((nt * 64 + j16 * 16 + lrow) * KP2 + kc * 16 + lcol) * 2);
                }
#pragma unroll
                for (int j = 0; j < 8; ++j) mma_f16(pc[j], qa, kb[j]);
            }

#pragma unroll
            for (int j = 0; j < 8; ++j) {
                const int n0 = nt * 64 + j * 8 + 2 * q;
                float f0 = (mrow >= n0)         ? pc[j][0] * expf(-s * (float)(mrow - n0))         : 0.0f;
                float f1 = (mrow >= n0 + 1)     ? pc[j][1] * expf(-s * (float)(mrow - n0 - 1))     : 0.0f;
                float f2 = (mrow + 8 >= n0)     ? pc[j][2] * expf(-s * (float)(mrow + 8 - n0))     : 0.0f;
                float f3 = (mrow + 8 >= n0 + 1) ? pc[j][3] * expf(-s * (float)(mrow + 8 - n0 - 1)) : 0.0f;
                __half2 h0 = __floats2half2_rn(f0, f1);
                __half2 h1 = __floats2half2_rn(f2, f3);
                *(__half2*)&Pw[r * PSTR + j * 8 + 2 * q]       = h0;
                *(__half2*)&Pw[(r + 8) * PSTR + j * 8 + 2 * q] = h1;
            }
            __syncwarp();

#pragma unroll
            for (int ks = 0; ks < 4; ++ks) {
                uint32_t pa[4], vb[16][2];
                ldsm_x4(pa[0], pa[1], pa[2], pa[3],
                        sPw + (lrow * PSTR + ks * 16 + lcol) * 2);
#pragma unroll
                for (int jj = 0; jj < 8; ++jj) {
                    ldsm_x4_t(vb[2 * jj][0], vb[2 * jj + 1][0],
                              vb[2 * jj][1], vb[2 * jj + 1][1],
                              sV + ((nt * 64 + ks * 16 + trow) * KP2 + jj * 16 + tcol) * 2);
                }
#pragma unroll
                for (int j = 0; j < 16; ++j) mma_f16(oc[tt][j], pa, vb[j]);
            }
            __syncwarp();
        }

        float* hb = g_hidden + (size_t)(b * BLK + mt * 16) * INNER + h * HD;
#pragma unroll
        for (int j = 0; j < 16; ++j) {
            const int e = j * 8 + 2 * q;
            *(float2*)(hb + (size_t)r * INNER + e)       = make_float2(oc[tt][j][0], oc[tt][j][1]);
            *(float2*)(hb + (size_t)(r + 8) * INNER + e) = make_float2(oc[tt][j][2], oc[tt][j][3]);
        }
    }
}

// ---------------- RMSNorm * weight * gate(fp16) -> fp16 ----------------
__global__ __launch_bounds__(256)
void rmsnorm_gate(const float* __restrict__ nw)
{
    const int m = blockIdx.x;
    const int t = threadIdx.x;
    const float* hrow = g_hidden + (size_t)m * INNER;
    const __half* grow = g_gateh + (size_t)m * INNER;
    __half* orow = g_ghalf + (size_t)m * INNER;

    float ss = 0.0f;
    for (int i = t; i < INNER / 4; i += 256) {
        float4 h4 = *(const float4*)(hrow + i * 4);
        ss += h4.x * h4.x + h4.y * h4.y + h4.z * h4.z + h4.w * h4.w;
    }
    __shared__ float red[256];
    red[t] = ss;
    __syncthreads();
    for (int s2 = 128; s2 > 0; s2 >>= 1) {
        if (t < s2) red[t] += red[t + s2];
        __syncthreads();
    }
    const float rs = rsqrtf(red[0] / (float)INNER + EPS_RMS);

    for (int i = t; i < INNER / 4; i += 256) {
        float4 h4 = *(const float4*)(hrow + i * 4);
        uint2 g2 = *(const uint2*)(grow + i * 4);
        float2 g0 = __half22float2(*(__half2*)&g2.x);
        float2 g1 = __half22float2(*(__half2*)&g2.y);
        float4 w4 = *(const float4*)(nw + i * 4);
        __half2 o0 = __floats2half2_rn(g0.x * (h4.x * rs * w4.x),
                                       g0.y * (h4.y * rs * w4.y));
        __half2 o1 = __floats2half2_rn(g1.x * (h4.z * rs * w4.z),
                                       g1.y * (h4.w * rs * w4.w));
        uint2 o;
        o.x = *(uint32_t*)&o0; o.y = *(uint32_t*)&o1;
        *(uint2*)(orow + i * 4) = o;
    }
}

// ---------------- launcher ----------------
extern "C" void kernel_launch(void* const* d_in, const int* in_sizes, int n_in,
                              void* d_out, int out_size)
{
    (void)in_sizes; (void)n_in; (void)out_size;
    const float* x     = (const float*)d_in[0];
    const float* wqkv  = (const float*)d_in[1];
    const float* wgate = (const float*)d_in[2];
    const float* wout  = (const float*)d_in[3];
    const float* nw    = (const float*)d_in[4];
    const float* kvc   = (const float*)d_in[5];
    const float* slope = (const float*)d_in[6];
    float* out = (float*)d_out;

    __half *p_xh = nullptr, *p_wqkvh = nullptr, *p_wgateh = nullptr,
           *p_wouth = nullptr, *p_ghalf = nullptr;
    cudaGetSymbolAddress((void**)&p_xh, g_xh);
    cudaGetSymbolAddress((void**)&p_wqkvh, g_wqkvh);
    cudaGetSymbolAddress((void**)&p_wgateh, g_wgateh);
    cudaGetSymbolAddress((void**)&p_wouth, g_wouth);
    cudaGetSymbolAddress((void**)&p_ghalf, g_ghalf);

    cudaFuncSetAttribute((const void*)gemm_qkvgate, cudaFuncAttributeMaxDynamicSharedMemorySize, GEMM_SMEM);
    cudaFuncSetAttribute((const void*)gemm_out,     cudaFuncAttributeMaxDynamicSharedMemorySize, GEMM_SMEM);
    cudaFuncSetAttribute((const void*)attn_out_mma, cudaFuncAttributeMaxDynamicSharedMemorySize, ATTNOUT_SMEM);

    // all fp32 -> fp16 conversions in one launch
    cvt_all_kernel<<<(N1 + N2 + N3 + N4) / 256, 256>>>(x, wqkv, wgate, wout,
                                                       p_xh, p_wqkvh, p_wgateh, p_wouth);

    // fused: qkv = silu(x@wqkv^T) -> fp16 ; gate = sigmoid(x@wgate^T) -> fp16
    gemm_qkvgate<<<dim3((QKVW + INNER) / BN, SEQ / BM), NTHR, GEMM_SMEM>>>(p_xh, p_wqkvh, p_wgateh);

    // lightning attention
    attn_kvblocks_mma<<<dim3(NB, NH), 128>>>(slope);
    attn_scan<<<(NH * HD * HD) / 256, 256>>>(kvc, slope);
    attn_out_mma<<<dim3(NB, NH), 256, ATTNOUT_SMEM>>>(slope);

    // rmsnorm * weight * gate -> fp16
    rmsnorm_gate<<<SEQ, 256>>>(nw);

    // out = (gate * normed) @ w_out^T
    gemm_out<<<dim3(HDIM / BN, SEQ / BM), NTHR, GEMM_SMEM>>>(p_ghalf, p_wouth, out);
}

// round 14
// speedup vs baseline: 1.0075x; 1.0075x over previous
#include <cuda_runtime.h>
#include <cuda_fp16.h>
#include <math.h>
#include <stdint.h>

#define SEQ   4096
#define HDIM  4096
#define INNER 4096
#define NH    32
#define HD    128
#define BLK   256
#define NB    16
#define QKVW  12288
#define EPS_RMS 1e-5f

#define GK    4096
#define BM    128
#define BN    128
#define BK    64
#define NTHR  128
#define KTILES (GK / BK)    // 64
#define KPADH 72
#define STGH_A (128 * KPADH)
#define STAGE_BYTES (2 * STGH_A * 2)    // 36864
#define NSTG  3
#define GEMM_SMEM (NSTG * STAGE_BYTES)  // 110592 -> 2 CTAs/SM

#define KP2   136
#define PSTR  72
#define ATTNOUT_SMEM (3 * 256 * KP2 * 2 + 8 * 16 * PSTR * 2)   // 227328

// ---------------- scratch ----------------
__device__ __half g_qkvh[(size_t)SEQ * QKVW];
__device__ __half g_hiddenh[(size_t)SEQ * INNER];   // fp16 attention output
__device__ __half g_gateh[(size_t)SEQ * INNER];
__device__ float  g_S[(size_t)NH * NB * HD * HD];
__device__ __half g_kvsth[(size_t)NH * NB * HD * HD];
__device__ __half g_xh[(size_t)SEQ * HDIM];
__device__ __half g_wqkvh[(size_t)QKVW * HDIM];
__device__ __half g_wgateh[(size_t)INNER * HDIM];
__device__ __half g_wouth[(size_t)HDIM * INNER];
__device__ __half g_ghalf[(size_t)SEQ * INNER];

// ---------------- helpers ----------------
__device__ __forceinline__ uint32_t smem_u32(const void* p) {
    uint32_t a;
    asm("{ .reg .u64 t; cvta.to.shared.u64 t, %1; cvt.u32.u64 %0, t; }" : "=r"(a) : "l"(p));
    return a;
}

__device__ __forceinline__ void cp_async16(uint32_t dst, const void* src) {
    asm volatile("cp.async.cg.shared.global [%0], [%1], 16;" :: "r"(dst), "l"(src));
}
#define CP_COMMIT() asm volatile("cp.async.commit_group;" ::: "memory")
#define CP_WAIT(n)  asm volatile("cp.async.wait_group %0;" :: "n"(n) : "memory")

__device__ __forceinline__ void ldsm_x4(uint32_t& r0, uint32_t& r1, uint32_t& r2, uint32_t& r3,
                                        uint32_t addr) {
    asm volatile("ldmatrix.sync.aligned.m8n8.x4.shared.b16 {%0,%1,%2,%3}, [%4];"
        : "=r"(r0), "=r"(r1), "=r"(r2), "=r"(r3) : "r"(addr));
}
__device__ __forceinline__ void ldsm_x4_t(uint32_t& r0, uint32_t& r1, uint32_t& r2, uint32_t& r3,
                                          uint32_t addr) {
    asm volatile("ldmatrix.sync.aligned.m8n8.x4.trans.shared.b16 {%0,%1,%2,%3}, [%4];"
        : "=r"(r0), "=r"(r1), "=r"(r2), "=r"(r3) : "r"(addr));
}

__device__ __forceinline__ void mma_f16(float* c, const uint32_t* a, const uint32_t* b) {
    asm volatile(
        "mma.sync.aligned.m16n8k16.row.col.f32.f16.f16.f32 "
        "{%0,%1,%2,%3}, {%4,%5,%6,%7}, {%8,%9}, {%0,%1,%2,%3};"
        : "+f"(c[0]), "+f"(c[1]), "+f"(c[2]), "+f"(c[3])
        : "r"(a[0]), "r"(a[1]), "r"(a[2]), "r"(a[3]), "r"(b[0]), "r"(b[1]));
}

__device__ __forceinline__ float silu_f(float v)  { return v / (1.0f + expf(-v)); }
__device__ __forceinline__ float sigm_f(float v)  { return 1.0f / (1.0f + expf(-v)); }

// ---------------- fused fp32 -> fp16 conversion ----------------
#define N1 (SEQ * HDIM / 8)
#define N2 (QKVW * HDIM / 8)
#define N3 (INNER * HDIM / 8)
#define N4 (HDIM * INNER / 8)
__global__ __launch_bounds__(256)
void cvt_all_kernel(const float* __restrict__ x,  const float* __restrict__ wq,
                    const float* __restrict__ wg, const float* __restrict__ wo,
                    __half* __restrict__ xh,  __half* __restrict__ wqh,
                    __half* __restrict__ wgh, __half* __restrict__ woh)
{
    int i = blockIdx.x * 256 + threadIdx.x;
    const float* in; __half* out; int j;
    if (i < N1)                { in = x;  out = xh;  j = i; }
    else if (i < N1 + N2)      { in = wq; out = wqh; j = i - N1; }
    else if (i < N1 + N2 + N3) { in = wg; out = wgh; j = i - N1 - N2; }
    else                       { in = wo; out = woh; j = i - N1 - N2 - N3; }
    float4 v0 = ((const float4*)in)[j * 2];
    float4 v1 = ((const float4*)in)[j * 2 + 1];
    __half2 h0 = __floats2half2_rn(v0.x, v0.y);
    __half2 h1 = __floats2half2_rn(v0.z, v0.w);
    __half2 h2 = __floats2half2_rn(v1.x, v1.y);
    __half2 h3 = __floats2half2_rn(v1.z, v1.w);
    uint4 o;
    o.x = *(uint32_t*)&h0; o.y = *(uint32_t*)&h1;
    o.z = *(uint32_t*)&h2; o.w = *(uint32_t*)&h3;
    ((uint4*)out)[j] = o;
}

// ---------------- GEMM mainloop (round-11 committed, frozen) ----------------
__device__ __forceinline__ void g_load_stage(uint32_t sbase, int slot, int s,
                                             const __half* __restrict__ Ab,
                                             const __half* __restrict__ Bb, int t)
{
    const uint32_t stA = sbase + slot * STAGE_BYTES;
    const uint32_t stB = stA + STGH_A * 2;
    const __half* ga = Ab + (size_t)s * BK;
    const __half* gb = Bb + (size_t)s * BK;
#pragma unroll
    for (int i = 0; i < 8; ++i) {
        int id = t + NTHR * i;
        int row = id >> 3, c = id & 7;
        cp_async16(stA + (row * KPADH + c * 8) * 2, ga + (size_t)row * GK + c * 8);
    }
#pragma unroll
    for (int i = 0; i < 8; ++i) {
        int id = t + NTHR * i;
        int row = id >> 3, c = id & 7;
        cp_async16(stB + (row * KPADH + c * 8) * 2, gb + (size_t)row * GK + c * 8);
    }
}

__device__ __forceinline__ void lds_frags(uint32_t sA, uint32_t sB, int k0,
                                          int wm, int wn, int r, int q,
                                          uint32_t af[4][4], uint32_t bf[8][2])
{
#pragma unroll
    for (int i = 0; i < 4; ++i) {
        uint32_t ap = sA + ((wm + i * 16 + r) * KPADH + k0 + 2 * q) * 2;
        asm volatile("ld.shared.b32 %0, [%1];" : "=r"(af[i][0]) : "r"(ap));
        asm volatile("ld.shared.b32 %0, [%1];" : "=r"(af[i][1]) : "r"(ap + 8 * KPADH * 2));
        asm volatile("ld.shared.b32 %0, [%1];" : "=r"(af[i][2]) : "r"(ap + 16));
        asm volatile("ld.shared.b32 %0, [%1];" : "=r"(af[i][3]) : "r"(ap + 8 * KPADH * 2 + 16));
    }
#pragma unroll
    for (int j = 0; j < 8; ++j) {
        uint32_t bp = sB + ((wn + j * 8 + r) * KPADH + k0 + 2 * q) * 2;
        asm volatile("ld.shared.b32 %0, [%1];" : "=r"(bf[j][0]) : "r"(bp));
        asm volatile("ld.shared.b32 %0, [%1];" : "=r"(bf[j][1]) : "r"(bp + 16));
    }
}

__device__ __forceinline__ void gemm_mainloop(uint32_t sbase, const __half* Ab,
                                              const __half* Bb, int t, int wm, int wn,
                                              int r, int q, float c[4][8][4])
{
#pragma unroll
    for (int i = 0; i < 4; ++i)
#pragma unroll
        for (int j = 0; j < 8; ++j)
#pragma unroll
            for (int p = 0; p < 4; ++p) c[i][j][p] = 0.0f;

    g_load_stage(sbase, 0, 0, Ab, Bb, t); CP_COMMIT();
    g_load_stage(sbase, 1, 1, Ab, Bb, t); CP_COMMIT();

    for (int s = 0; s < KTILES; ++s) {
        const int slot = s % NSTG;
        CP_WAIT(1);
        __syncthreads();

        if (s + 2 < KTILES) {
            g_load_stage(sbase, (s + 2) % NSTG, s + 2, Ab, Bb, t);
        }
        CP_COMMIT();

        const uint32_t sA = sbase + slot * STAGE_BYTES;
        const uint32_t sB = sA + STGH_A * 2;

        uint32_t af[2][4][4], bf[2][8][2];
        lds_frags(sA, sB, 0, wm, wn, r, q, af[0], bf[0]);
#pragma unroll
        for (int ks = 0; ks < 4; ++ks) {
            if (ks < 3)
                lds_frags(sA, sB, (ks + 1) * 16, wm, wn, r, q,
                          af[(ks + 1) & 1], bf[(ks + 1) & 1]);
#pragma unroll
            for (int i = 0; i < 4; ++i)
#pragma unroll
                for (int j = 0; j < 8; ++j)
                    mma_f16(c[i][j], af[ks & 1][i], bf[ks & 1][j]);
        }
    }
}

// ---------------- fused GEMM1+GEMM2 ----------------
__global__ __launch_bounds__(NTHR, 2)
void gemm_qkvgate(const __half* __restrict__ A,
                  const __half* __restrict__ Bq, const __half* __restrict__ Bg)
{
    extern __shared__ __align__(128) __half smem[];
    const uint32_t sbase = smem_u32(smem);
    const int t    = threadIdx.x;
    const int wid  = t >> 5;
    const int lane = t & 31;
    const int bm = blockIdx.y * BM;
    const int bn = blockIdx.x * BN;

    const bool is_q = (bn < QKVW);
    const int  cbase = is_q ? bn : (bn - QKVW);
    const __half* Bb = (is_q ? Bq : Bg) + (size_t)cbase * GK;
    __half* Ch = (is_q ? g_qkvh : g_gateh);
    const int Ntot = is_q ? QKVW : INNER;
    const __half* Ab = A + (size_t)bm * GK;

    const int wm = (wid & 1) * 64;
    const int wn = (wid >> 1) * 64;
    const int r  = lane >> 2;
    const int q  = lane & 3;

    float c[4][8][4];
    gemm_mainloop(sbase, Ab, Bb, t, wm, wn, r, q, c);

#pragma unroll
    for (int i = 0; i < 4; ++i) {
        const int row0 = bm + wm + i * 16 + r;
#pragma unroll
        for (int j = 0; j < 8; ++j) {
            const int col = cbase + wn + j * 8 + 2 * q;
            float f0, f1, f2, f3;
            if (is_q) {
                f0 = silu_f(c[i][j][0]); f1 = silu_f(c[i][j][1]);
                f2 = silu_f(c[i][j][2]); f3 = silu_f(c[i][j][3]);
            } else {
                f0 = sigm_f(c[i][j][0]); f1 = sigm_f(c[i][j][1]);
                f2 = sigm_f(c[i][j][2]); f3 = sigm_f(c[i][j][3]);
            }
            __half2 h0 = __floats2half2_rn(f0, f1);
            __half2 h1 = __floats2half2_rn(f2, f3);
            *(__half2*)(Ch + (size_t)row0 * Ntot + col)       = h0;
            *(__half2*)(Ch + (size_t)(row0 + 8) * Ntot + col) = h1;
        }
    }
}

// ---------------- GEMM3 ----------------
__global__ __launch_bounds__(NTHR, 2)
void gemm_out(const __half* __restrict__ A, const __half* __restrict__ B,
              float* __restrict__ C)
{
    extern __shared__ __align__(128) __half smem[];
    const uint32_t sbase = smem_u32(smem);
    const int t    = threadIdx.x;
    const int wid  = t >> 5;
    const int lane = t & 31;
    const int bm = blockIdx.y * BM;
    const int bn = blockIdx.x * BN;
    const __half* Ab = A + (size_t)bm * GK;
    const __half* Bb = B + (size_t)bn * GK;

    const int wm = (wid & 1) * 64;
    const int wn = (wid >> 1) * 64;
    const int r  = lane >> 2;
    const int q  = lane & 3;

    float c[4][8][4];
    gemm_mainloop(sbase, Ab, Bb, t, wm, wn, r, q, c);

#pragma unroll
    for (int i = 0; i < 4; ++i) {
        const int row0 = bm + wm + i * 16 + r;
#pragma unroll
        for (int j = 0; j < 8; ++j) {
            const int col = bn + wn + j * 8 + 2 * q;
            *(float2*)(C + (size_t)row0 * HDIM + col)       = make_float2(c[i][j][0], c[i][j][1]);
            *(float2*)(C + (size_t)(row0 + 8) * HDIM + col) = make_float2(c[i][j][2], c[i][j][3]);
        }
    }
}

// ---------------- attention stage A (fp16 mma) ----------------
__global__ __launch_bounds__(128)
void attn_kvblocks_mma(const float* __restrict__ slope)
{
    const int b = blockIdx.x;
    const int h = blockIdx.y;
    const float s = slope[h];

    __shared__ __half Ks[64][KP2];
    __shared__ __half Vs[64][KP2];

    const int t = threadIdx.x;
    const int w = t >> 5, lane = t & 31;
    const int wm = w * 32;
    const int r = lane >> 2, q = lane & 3;
    const int trow = (lane & 7) + ((lane >> 4) & 1) * 8;
    const int tcol = ((lane >> 3) & 1) * 8;

    const __half* kbase = g_qkvh + (size_t)(b * BLK) * QKVW + h * 384 + 128;
    const __half* vbase = kbase + 128;

    const uint32_t sK = smem_u32(Ks);
    const uint32_t sV = smem_u32(Vs);

    float c[2][16][4];
#pragma unroll
    for (int i = 0; i < 2; ++i)
#pragma unroll
        for (int j = 0; j < 16; ++j)
#pragma unroll
            for (int p = 0; p < 4; ++p) c[i][j][p] = 0.0f;

    for (int ch = 0; ch < 4; ++ch) {
        __syncthreads();
#pragma unroll
        for (int it = 0; it < 8; ++it) {
            int id = t + 128 * it;
            int row = id >> 4;
            int c16 = id & 15;
            int i = ch * 64 + row;
            float kd = expf(-s * (float)(255 - i));
            uint4 k4 = *(const uint4*)(kbase + (size_t)i * QKVW + c16 * 8);
            __half2* hp = (__half2*)&k4;
#pragma unroll
            for (int z = 0; z < 4; ++z) {
                float2 f = __half22float2(hp[z]);
                hp[z] = __floats2half2_rn(f.x * kd, f.y * kd);
            }
            *(uint4*)&Ks[row][c16 * 8] = k4;
            uint4 v4 = *(const uint4*)(vbase + (size_t)i * QKVW + c16 * 8);
            *(uint4*)&Vs[row][c16 * 8] = v4;
        }
        __syncthreads();

#pragma unroll
        for (int kc = 0; kc < 4; ++kc) {
            uint32_t af[2][4], bf[16][2];
#pragma unroll
            for (int i16 = 0; i16 < 2; ++i16) {
                uint32_t addr = sK + ((kc * 16 + trow) * KP2 + wm + i16 * 16 + tcol) * 2;
                ldsm_x4_t(af[i16][0], af[i16][1], af[i16][2], af[i16][3], addr);
            }
#pragma unroll
            for (int jj = 0; jj < 8; ++jj) {
                uint32_t addr = sV + ((kc * 16 + trow) * KP2 + jj * 16 + tcol) * 2;
                ldsm_x4_t(bf[2 * jj][0], bf[2 * jj + 1][0], bf[2 * jj][1], bf[2 * jj + 1][1], addr);
            }
#pragma unroll
            for (int i16 = 0; i16 < 2; ++i16)
#pragma unroll
                for (int j = 0; j < 16; ++j)
                    mma_f16(c[i16][j], af[i16], bf[j]);
        }
    }

    float* Sp = g_S + (size_t)(h * NB + b) * HD * HD;
#pragma unroll
    for (int i16 = 0; i16 < 2; ++i16) {
        const int d0 = wm + i16 * 16 + r;
#pragma unroll
        for (int j = 0; j < 16; ++j) {
            const int e = j * 8 + 2 * q;
            *(float2*)(Sp + (size_t)d0 * HD + e)       = make_float2(c[i16][j][0], c[i16][j][1]);
            *(float2*)(Sp + (size_t)(d0 + 8) * HD + e) = make_float2(c[i16][j][2], c[i16][j][3]);
        }
    }
}

// ---------------- attention stage B (fp32 scan, MLP prefetch, fp16 out) ----------------
__global__ void attn_scan(const float* __restrict__ kv_cache, const float* __restrict__ slope)
{
    const int g = blockIdx.x * 256 + threadIdx.x;
    const int h = g >> 14;
    const int e = g & 16383;
    const float dec = expf(-slope[h] * 256.0f);
    const size_t base = (size_t)h * NB * 16384 + e;

    float sv[NB];
#pragma unroll
    for (int b = 0; b < NB; ++b)
        sv[b] = g_S[base + (size_t)b * 16384];

    float c = kv_cache[(size_t)h * 16384 + e];
#pragma unroll
    for (int b = 0; b < NB; ++b) {
        g_kvsth[base + (size_t)b * 16384] = __float2half_rn(c);
        c = dec * c + sv[b];
    }
}

// ---------------- fused attention output (fp16 hidden store) ----------------
__global__ __launch_bounds__(256, 1)
void attn_out_mma(const float* __restrict__ slope)
{
    extern __shared__ __align__(128) __half osm[];
    const uint32_t sQ = smem_u32(osm);
    const uint32_t sK = sQ + 256 * KP2 * 2;
    const uint32_t sV = sK + 256 * KP2 * 2;
    const uint32_t sP = sV + 256 * KP2 * 2;

    const int b = blockIdx.x;
    const int h = blockIdx.y;
    const float s = slope[h];

    const int t = threadIdx.x;
    const int w = t >> 5, lane = t & 31;
    const int r = lane >> 2, q = lane & 3;
    const int lrow = (lane & 7) + ((lane >> 3) & 1) * 8;
    const int lcol = (lane >> 4) * 8;
    const int trow = (lane & 7) + ((lane >> 4) & 1) * 8;
    const int tcol = ((lane >> 3) & 1) * 8;

    const __half* qkv = g_qkvh + (size_t)(b * BLK) * QKVW + h * 384;
    const __half* kvst = g_kvsth + (size_t)(h * NB + b) * HD * HD;

    __half* Qs = (__half*)osm;
    __half* KVs = Qs + 256 * KP2;

#pragma unroll
    for (int it = 0; it < 16; ++it) {
        int id = t + 256 * it;
        int row = id >> 4, c16 = id & 15;
        *(uint4*)&Qs[row * KP2 + c16 * 8] = *(const uint4*)(qkv + (size_t)row * QKVW + c16 * 8);
    }
#pragma unroll
    for (int it = 0; it < 8; ++it) {
        int id = t + 256 * it;
        int row = id >> 4, c16 = id & 15;
        *(uint4*)&KVs[row * KP2 + c16 * 8] = *(const uint4*)(kvst + (size_t)row * HD + c16 * 8);
    }
    __syncthreads();

    float oc[2][16][4];
#pragma unroll
    for (int tt = 0; tt < 2; ++tt) {
        const int mt = (tt == 0) ? w : (15 - w);
#pragma unroll
        for (int j = 0; j < 16; ++j)
#pragma unroll
            for (int p = 0; p < 4; ++p) oc[tt][j][p] = 0.0f;

#pragma unroll
        for (int kc = 0; kc < 8; ++kc) {
            uint32_t qa[4], bf[16][2];
            ldsm_x4(qa[0], qa[1], qa[2], qa[3],
                    sQ + ((mt * 16 + lrow) * KP2 + kc * 16 + lcol) * 2);
#pragma unroll
            for (int jj = 0; jj < 8; ++jj) {
                ldsm_x4_t(bf[2 * jj][0], bf[2 * jj + 1][0],
                          bf[2 * jj][1], bf[2 * jj + 1][1],
                          sK + ((kc * 16 + trow) * KP2 + jj * 16 + tcol) * 2);
            }
#pragma unroll
            for (int j = 0; j < 16; ++j) mma_f16(oc[tt][j], qa, bf[j]);
        }

        const int mrow = mt * 16 + r;
        const float qd0 = expf(-s * (float)(mrow + 1));
        const float qd8 = expf(-s * (float)(mrow + 9));
#pragma unroll
        for (int j = 0; j < 16; ++j) {
            oc[tt][j][0] *= qd0; oc[tt][j][1] *= qd0;
            oc[tt][j][2] *= qd8; oc[tt][j][3] *= qd8;
        }
    }
    __syncthreads();

    __half* Ks = KVs;
    __half* Vs = Ks + 256 * KP2;
#pragma unroll
    for (int it = 0; it < 16; ++it) {
        int id = t + 256 * it;
        int row = id >> 4, c16 = id & 15;
        *(uint4*)&Ks[row * KP2 + c16 * 8] = *(const uint4*)(qkv + 128 + (size_t)row * QKVW + c16 * 8);
        *(uint4*)&Vs[row * KP2 + c16 * 8] = *(const uint4*)(qkv + 256 + (size_t)row * QKVW + c16 * 8);
    }
    __syncthreads();

    const uint32_t sPw = sP + w * 16 * PSTR * 2;
    __half* Pw = (__half*)(osm) + (sPw - sQ) / 2;

#pragma unroll
    for (int tt = 0; tt < 2; ++tt) {
        const int mt = (tt == 0) ? w : (15 - w);
        const int mrow = mt * 16 + r;

        const int nchunks = mt / 4 + 1;
        for (int nt = 0; nt < nchunks; ++nt) {
            float pc[8][4];
#pragma unroll
            for (int j = 0; j < 8; ++j)
#pragma unroll
                for (int p = 0; p < 4; ++p) pc[j][p] = 0.0f;

#pragma unroll
            for (int kc = 0; kc < 8; ++kc) {
                uint32_t qa[4], kb[8][2];
                ldsm_x4(qa[0], qa[1], qa[2], qa[3],
                        sQ + ((mt * 16 + lrow) * KP2 + kc * 16 + lcol) * 2);
#pragma unroll
                for (int j16 = 0; j16 < 4; ++j16) {
                    ldsm_x4(kb[2 * j16][0], kb[2 * j16 + 1][0],
                            kb[2 * j16][1], kb[2 * j16 + 1][1],
                            sK + ((nt * 64 + j16 * 16 + lrow) * KP2 + kc * 16 + lcol) * 2);
                }
#pragma unroll
                for (int j = 0; j < 8; ++j) mma_f16(pc[j], qa, kb[j]);
            }

#pragma unroll
            for (int j = 0; j < 8; ++j) {
                const int n0 = nt * 64 + j * 8 + 2 * q;
                float f0 = (mrow >= n0)         ? pc[j][0] * expf(-s * (float)(mrow - n0))         : 0.0f;
                float f1 = (mrow >= n0 + 1)     ? pc[j][1] * expf(-s * (float)(mrow - n0 - 1))     : 0.0f;
                float f2 = (mrow + 8 >= n0)     ? pc[j][2] * expf(-s * (float)(mrow + 8 - n0))     : 0.0f;
                float f3 = (mrow + 8 >= n0 + 1) ? pc[j][3] * expf(-s * (float)(mrow + 8 - n0 - 1)) : 0.0f;
                __half2 h0 = __floats2half2_rn(f0, f1);
                __half2 h1 = __floats2half2_rn(f2, f3);
                *(__half2*)&Pw[r * PSTR + j * 8 + 2 * q]       = h0;
                *(__half2*)&Pw[(r + 8) * PSTR + j * 8 + 2 * q] = h1;
            }
            __syncwarp();

#pragma unroll
            for (int ks = 0; ks < 4; ++ks) {
                uint32_t pa[4], vb[16][2];
                ldsm_x4(pa[0], pa[1], pa[2], pa[3],
                        sPw + (lrow * PSTR + ks * 16 + lcol) * 2);
#pragma unroll
                for (int jj = 0; jj < 8; ++jj) {
                    ldsm_x4_t(vb[2 * jj][0], vb[2 * jj + 1][0],
                              vb[2 * jj][1], vb[2 * jj + 1][1],
                              sV + ((nt * 64 + ks * 16 + trow) * KP2 + jj * 16 + tcol) * 2);
                }
#pragma unroll
                for (int j = 0; j < 16; ++j) mma_f16(oc[tt][j], pa, vb[j]);
            }
            __syncwarp();
        }

        // single fp16 store (no RMW)
        __half* hb = g_hiddenh + (size_t)(b * BLK + mt * 16) * INNER + h * HD;
#pragma unroll
        for (int j = 0; j < 16; ++j) {
            const int e = j * 8 + 2 * q;
            __half2 h0 = __floats2half2_rn(oc[tt][j][0], oc[tt][j][1]);
            __half2 h1 = __floats2half2_rn(oc[tt][j][2], oc[tt][j][3]);
            *(__half2*)(hb + (size_t)r * INNER + e)       = h0;
            *(__half2*)(hb + (size_t)(r + 8) * INNER + e) = h1;
        }
    }
}

// ---------------- RMSNorm * weight * gate (both fp16 in) -> fp16 ----------------
__global__ __launch_bounds__(256)
void rmsnorm_gate(const float* __restrict__ nw)
{
    const int m = blockIdx.x;
    const int t = threadIdx.x;
    const __half* hrow = g_hiddenh + (size_t)m * INNER;
    const __half* grow = g_gateh + (size_t)m * INNER;
    __half* orow = g_ghalf + (size_t)m * INNER;

    float ss = 0.0f;
    for (int i = t; i < INNER / 4; i += 256) {
        uint2 h2 = *(const uint2*)(hrow + i * 4);
        float2 a = __half22float2(*(__half2*)&h2.x);
        float2 bb = __half22float2(*(__half2*)&h2.y);
        ss += a.x * a.x + a.y * a.y + bb.x * bb.x + bb.y * bb.y;
    }
    __shared__ float red[256];
    red[t] = ss;
    __syncthreads();
    for (int s2 = 128; s2 > 0; s2 >>= 1) {
        if (t < s2) red[t] += red[t + s2];
        __syncthreads();
    }
    const float rs = rsqrtf(red[0] / (float)INNER + EPS_RMS);

    for (int i = t; i < INNER / 4; i += 256) {
        uint2 h2 = *(const uint2*)(hrow + i * 4);
        float2 a = __half22float2(*(__half2*)&h2.x);
        float2 bb = __half22float2(*(__half2*)&h2.y);
        uint2 g2 = *(const uint2*)(grow + i * 4);
        float2 g0 = __half22float2(*(__half2*)&g2.x);
        float2 g1 = __half22float2(*(__half2*)&g2.y);
        float4 w4 = *(const float4*)(nw + i * 4);
        __half2 o0 = __floats2half2_rn(g0.x * (a.x * rs * w4.x),
                                       g0.y * (a.y * rs * w4.y));
        __half2 o1 = __floats2half2_rn(g1.x * (bb.x * rs * w4.z),
                                       g1.y * (bb.y * rs * w4.w));
        uint2 o;
        o.x = *(uint32_t*)&o0; o.y = *(uint32_t*)&o1;
        *(uint2*)(orow + i * 4) = o;
    }
}

// ---------------- launcher ----------------
extern "C" void kernel_launch(void* const* d_in, const int* in_sizes, int n_in,
                              void* d_out, int out_size)
{
    (void)in_sizes; (void)n_in; (void)out_size;
    const float* x     = (const float*)d_in[0];
    const float* wqkv  = (const float*)d_in[1];
    const float* wgate = (const float*)d_in[2];
    const float* wout  = (const float*)d_in[3];
    const float* nw    = (const float*)d_in[4];
    const float* kvc   = (const float*)d_in[5];
    const float* slope = (const float*)d_in[6];
    float* out = (float*)d_out;

    __half *p_xh = nullptr, *p_wqkvh = nullptr, *p_wgateh = nullptr,
           *p_wouth = nullptr, *p_ghalf = nullptr;
    cudaGetSymbolAddress((void**)&p_xh, g_xh);
    cudaGetSymbolAddress((void**)&p_wqkvh, g_wqkvh);
    cudaGetSymbolAddress((void**)&p_wgateh, g_wgateh);
    cudaGetSymbolAddress((void**)&p_wouth, g_wouth);
    cudaGetSymbolAddress((void**)&p_ghalf, g_ghalf);

    cudaFuncSetAttribute((const void*)gemm_qkvgate, cudaFuncAttributeMaxDynamicSharedMemorySize, GEMM_SMEM);
    cudaFuncSetAttribute((const void*)gemm_out,     cudaFuncAttributeMaxDynamicSharedMemorySize, GEMM_SMEM);
    cudaFuncSetAttribute((const void*)attn_out_mma, cudaFuncAttributeMaxDynamicSharedMemorySize, ATTNOUT_SMEM);

    // all fp32 -> fp16 conversions in one launch
    cvt_all_kernel<<<(N1 + N2 + N3 + N4) / 256, 256>>>(x, wqkv, wgate, wout,
                                                       p_xh, p_wqkvh, p_wgateh, p_wouth);

    // fused: qkv = silu(x@wqkv^T) -> fp16 ; gate = sigmoid(x@wgate^T) -> fp16
    gemm_qkvgate<<<dim3((QKVW + INNER) / BN, SEQ / BM), NTHR, GEMM_SMEM>>>(p_xh, p_wqkvh, p_wgateh);

    // lightning attention
    attn_kvblocks_mma<<<dim3(NB, NH), 128>>>(slope);
    attn_scan<<<(NH * HD * HD) / 256, 256>>>(kvc, slope);
    attn_out_mma<<<dim3(NB, NH), 256, ATTNOUT_SMEM>>>(slope);

    // rmsnorm * weight * gate -> fp16
    rmsnorm_gate<<<SEQ, 256>>>(nw);

    // out = (gate * normed) @ w_out^T
    gemm_out<<<dim3(HDIM / BN, SEQ / BM), NTHR, GEMM_SMEM>>>(p_ghalf, p_wouth, out);
}

// round 15
// speedup vs baseline: 1.0075x; 1.0001x over previous
#include <cuda_runtime.h>
#include <cuda_fp16.h>
#include <math.h>
#include <stdint.h>

#define SEQ   4096
#define HDIM  4096
#define INNER 4096
#define NH    32
#define HD    128
#define BLK   256
#define NB    16
#define QKVW  12288
#define EPS_RMS 1e-5f

#define GK    4096
#define BM    128
#define BN    128
#define BK    64
#define NTHR  128
#define KTILES (GK / BK)    // 64
#define KPADH 72
#define STGH_A (128 * KPADH)
#define STAGE_BYTES (2 * STGH_A * 2)    // 36864
#define NSTG  3
#define GEMM_SMEM (NSTG * STAGE_BYTES)  // 110592 -> 2 CTAs/SM

#define KP2   136
#define PSTR  72
#define ATTNOUT_SMEM (3 * 256 * KP2 * 2 + 8 * 16 * PSTR * 2)   // 227328

// ---------------- scratch ----------------
__device__ __half g_qkvh[(size_t)SEQ * QKVW];
__device__ __half g_hiddenh[(size_t)SEQ * INNER];
__device__ __half g_gateh[(size_t)SEQ * INNER];
__device__ float  g_S[(size_t)NH * NB * HD * HD];
__device__ __half g_kvsth[(size_t)NH * NB * HD * HD];
__device__ __half g_xh[(size_t)SEQ * HDIM];
__device__ __half g_wqkvh[(size_t)QKVW * HDIM];
__device__ __half g_wgateh[(size_t)INNER * HDIM];
__device__ __half g_wouth[(size_t)HDIM * INNER];
__device__ __half g_ghalf[(size_t)SEQ * INNER];

// ---------------- helpers ----------------
__device__ __forceinline__ uint32_t smem_u32(const void* p) {
    uint32_t a;
    asm("{ .reg .u64 t; cvta.to.shared.u64 t, %1; cvt.u32.u64 %0, t; }" : "=r"(a) : "l"(p));
    return a;
}

__device__ __forceinline__ void cp_async16(uint32_t dst, const void* src) {
    asm volatile("cp.async.cg.shared.global [%0], [%1], 16;" :: "r"(dst), "l"(src));
}
#define CP_COMMIT() asm volatile("cp.async.commit_group;" ::: "memory")
#define CP_WAIT(n)  asm volatile("cp.async.wait_group %0;" :: "n"(n) : "memory")

__device__ __forceinline__ void ldsm_x4(uint32_t& r0, uint32_t& r1, uint32_t& r2, uint32_t& r3,
                                        uint32_t addr) {
    asm volatile("ldmatrix.sync.aligned.m8n8.x4.shared.b16 {%0,%1,%2,%3}, [%4];"
        : "=r"(r0), "=r"(r1), "=r"(r2), "=r"(r3) : "r"(addr));
}
__device__ __forceinline__ void ldsm_x4_t(uint32_t& r0, uint32_t& r1, uint32_t& r2, uint32_t& r3,
                                          uint32_t addr) {
    asm volatile("ldmatrix.sync.aligned.m8n8.x4.trans.shared.b16 {%0,%1,%2,%3}, [%4];"
        : "=r"(r0), "=r"(r1), "=r"(r2), "=r"(r3) : "r"(addr));
}

__device__ __forceinline__ void mma_f16(float* c, const uint32_t* a, const uint32_t* b) {
    asm volatile(
        "mma.sync.aligned.m16n8k16.row.col.f32.f16.f16.f32 "
        "{%0,%1,%2,%3}, {%4,%5,%6,%7}, {%8,%9}, {%0,%1,%2,%3};"
        : "+f"(c[0]), "+f"(c[1]), "+f"(c[2]), "+f"(c[3])
        : "r"(a[0]), "r"(a[1]), "r"(a[2]), "r"(a[3]), "r"(b[0]), "r"(b[1]));
}

__device__ __forceinline__ float silu_f(float v)  { return v / (1.0f + expf(-v)); }
__device__ __forceinline__ float sigm_f(float v)  { return 1.0f / (1.0f + expf(-v)); }

// ---------------- fused fp32 -> fp16 conversion (16 floats/thread, MLP=4) ----------------
#define M1 (SEQ * HDIM / 16)
#define M2 (QKVW * HDIM / 16)
#define M3 (INNER * HDIM / 16)
#define M4 (HDIM * INNER / 16)
__device__ __forceinline__ uint2 cvt8(float4 v0, float4 v1) {
    __half2 h0 = __floats2half2_rn(v0.x, v0.y);
    __half2 h1 = __floats2half2_rn(v0.z, v0.w);
    __half2 h2 = __floats2half2_rn(v1.x, v1.y);
    __half2 h3 = __floats2half2_rn(v1.z, v1.w);
    (void)h2; (void)h3;
    uint2 o;
    o.x = *(uint32_t*)&h0; o.y = *(uint32_t*)&h1;
    return o;
}

__global__ __launch_bounds__(256)
void cvt_all_kernel(const float* __restrict__ x,  const float* __restrict__ wq,
                    const float* __restrict__ wg, const float* __restrict__ wo,
                    __half* __restrict__ xh,  __half* __restrict__ wqh,
                    __half* __restrict__ wgh, __half* __restrict__ woh)
{
    int i = blockIdx.x * 256 + threadIdx.x;
    const float* in; __half* out; int j;
    if (i < M1)                { in = x;  out = xh;  j = i; }
    else if (i < M1 + M2)      { in = wq; out = wqh; j = i - M1; }
    else if (i < M1 + M2 + M3) { in = wg; out = wgh; j = i - M1 - M2; }
    else                       { in = wo; out = woh; j = i - M1 - M2 - M3; }
    // 4 independent loads in flight
    float4 v0 = ((const float4*)in)[j * 4 + 0];
    float4 v1 = ((const float4*)in)[j * 4 + 1];
    float4 v2 = ((const float4*)in)[j * 4 + 2];
    float4 v3 = ((const float4*)in)[j * 4 + 3];
    __half2 a0 = __floats2half2_rn(v0.x, v0.y), a1 = __floats2half2_rn(v0.z, v0.w);
    __half2 a2 = __floats2half2_rn(v1.x, v1.y), a3 = __floats2half2_rn(v1.z, v1.w);
    __half2 b0 = __floats2half2_rn(v2.x, v2.y), b1 = __floats2half2_rn(v2.z, v2.w);
    __half2 b2 = __floats2half2_rn(v3.x, v3.y), b3 = __floats2half2_rn(v3.z, v3.w);
    uint4 o0, o1;
    o0.x = *(uint32_t*)&a0; o0.y = *(uint32_t*)&a1;
    o0.z = *(uint32_t*)&a2; o0.w = *(uint32_t*)&a3;
    o1.x = *(uint32_t*)&b0; o1.y = *(uint32_t*)&b1;
    o1.z = *(uint32_t*)&b2; o1.w = *(uint32_t*)&b3;
    ((uint4*)out)[j * 2 + 0] = o0;
    ((uint4*)out)[j * 2 + 1] = o1;
}

// ---------------- GEMM mainloop (frozen) ----------------
__device__ __forceinline__ void g_load_stage(uint32_t sbase, int slot, int s,
                                             const __half* __restrict__ Ab,
                                             const __half* __restrict__ Bb, int t)
{
    const uint32_t stA = sbase + slot * STAGE_BYTES;
    const uint32_t stB = stA + STGH_A * 2;
    const __half* ga = Ab + (size_t)s * BK;
    const __half* gb = Bb + (size_t)s * BK;
#pragma unroll
    for (int i = 0; i < 8; ++i) {
        int id = t + NTHR * i;
        int row = id >> 3, c = id & 7;
        cp_async16(stA + (row * KPADH + c * 8) * 2, ga + (size_t)row * GK + c * 8);
    }
#pragma unroll
    for (int i = 0; i < 8; ++i) {
        int id = t + NTHR * i;
        int row = id >> 3, c = id & 7;
        cp_async16(stB + (row * KPADH + c * 8) * 2, gb + (size_t)row * GK + c * 8);
    }
}

__device__ __forceinline__ void lds_frags(uint32_t sA, uint32_t sB, int k0,
                                          int wm, int wn, int r, int q,
                                          uint32_t af[4][4], uint32_t bf[8][2])
{
#pragma unroll
    for (int i = 0; i < 4; ++i) {
        uint32_t ap = sA + ((wm + i * 16 + r) * KPADH + k0 + 2 * q) * 2;
        asm volatile("ld.shared.b32 %0, [%1];" : "=r"(af[i][0]) : "r"(ap));
        asm volatile("ld.shared.b32 %0, [%1];" : "=r"(af[i][1]) : "r"(ap + 8 * KPADH * 2));
        asm volatile("ld.shared.b32 %0, [%1];" : "=r"(af[i][2]) : "r"(ap + 16));
        asm volatile("ld.shared.b32 %0, [%1];" : "=r"(af[i][3]) : "r"(ap + 8 * KPADH * 2 + 16));
    }
#pragma unroll
    for (int j = 0; j < 8; ++j) {
        uint32_t bp = sB + ((wn + j * 8 + r) * KPADH + k0 + 2 * q) * 2;
        asm volatile("ld.shared.b32 %0, [%1];" : "=r"(bf[j][0]) : "r"(bp));
        asm volatile("ld.shared.b32 %0, [%1];" : "=r"(bf[j][1]) : "r"(bp + 16));
    }
}

__device__ __forceinline__ void gemm_mainloop(uint32_t sbase, const __half* Ab,
                                              const __half* Bb, int t, int wm, int wn,
                                              int r, int q, float c[4][8][4])
{
#pragma unroll
    for (int i = 0; i < 4; ++i)
#pragma unroll
        for (int j = 0; j < 8; ++j)
#pragma unroll
            for (int p = 0; p < 4; ++p) c[i][j][p] = 0.0f;

    g_load_stage(sbase, 0, 0, Ab, Bb, t); CP_COMMIT();
    g_load_stage(sbase, 1, 1, Ab, Bb, t); CP_COMMIT();

    for (int s = 0; s < KTILES; ++s) {
        const int slot = s % NSTG;
        CP_WAIT(1);
        __syncthreads();

        if (s + 2 < KTILES) {
            g_load_stage(sbase, (s + 2) % NSTG, s + 2, Ab, Bb, t);
        }
        CP_COMMIT();

        const uint32_t sA = sbase + slot * STAGE_BYTES;
        const uint32_t sB = sA + STGH_A * 2;

        uint32_t af[2][4][4], bf[2][8][2];
        lds_frags(sA, sB, 0, wm, wn, r, q, af[0], bf[0]);
#pragma unroll
        for (int ks = 0; ks < 4; ++ks) {
            if (ks < 3)
                lds_frags(sA, sB, (ks + 1) * 16, wm, wn, r, q,
                          af[(ks + 1) & 1], bf[(ks + 1) & 1]);
#pragma unroll
            for (int i = 0; i < 4; ++i)
#pragma unroll
                for (int j = 0; j < 8; ++j)
                    mma_f16(c[i][j], af[ks & 1][i], bf[ks & 1][j]);
        }
    }
}

// ---------------- fused GEMM1+GEMM2 ----------------
__global__ __launch_bounds__(NTHR, 2)
void gemm_qkvgate(const __half* __restrict__ A,
                  const __half* __restrict__ Bq, const __half* __restrict__ Bg)
{
    extern __shared__ __align__(128) __half smem[];
    const uint32_t sbase = smem_u32(smem);
    const int t    = threadIdx.x;
    const int wid  = t >> 5;
    const int lane = t & 31;
    const int bm = blockIdx.y * BM;
    const int bn = blockIdx.x * BN;

    const bool is_q = (bn < QKVW);
    const int  cbase = is_q ? bn : (bn - QKVW);
    const __half* Bb = (is_q ? Bq : Bg) + (size_t)cbase * GK;
    __half* Ch = (is_q ? g_qkvh : g_gateh);
    const int Ntot = is_q ? QKVW : INNER;
    const __half* Ab = A + (size_t)bm * GK;

    const int wm = (wid & 1) * 64;
    const int wn = (wid >> 1) * 64;
    const int r  = lane >> 2;
    const int q  = lane & 3;

    float c[4][8][4];
    gemm_mainloop(sbase, Ab, Bb, t, wm, wn, r, q, c);

#pragma unroll
    for (int i = 0; i < 4; ++i) {
        const int row0 = bm + wm + i * 16 + r;
#pragma unroll
        for (int j = 0; j < 8; ++j) {
            const int col = cbase + wn + j * 8 + 2 * q;
            float f0, f1, f2, f3;
            if (is_q) {
                f0 = silu_f(c[i][j][0]); f1 = silu_f(c[i][j][1]);
                f2 = silu_f(c[i][j][2]); f3 = silu_f(c[i][j][3]);
            } else {
                f0 = sigm_f(c[i][j][0]); f1 = sigm_f(c[i][j][1]);
                f2 = sigm_f(c[i][j][2]); f3 = sigm_f(c[i][j][3]);
            }
            __half2 h0 = __floats2half2_rn(f0, f1);
            __half2 h1 = __floats2half2_rn(f2, f3);
            *(__half2*)(Ch + (size_t)row0 * Ntot + col)       = h0;
            *(__half2*)(Ch + (size_t)(row0 + 8) * Ntot + col) = h1;
        }
    }
}

// ---------------- GEMM3 ----------------
__global__ __launch_bounds__(NTHR, 2)
void gemm_out(const __half* __restrict__ A, const __half* __restrict__ B,
              float* __restrict__ C)
{
    extern __shared__ __align__(128) __half smem[];
    const uint32_t sbase = smem_u32(smem);
    const int t    = threadIdx.x;
    const int wid  = t >> 5;
    const int lane = t & 31;
    const int bm = blockIdx.y * BM;
    const int bn = blockIdx.x * BN;
    const __half* Ab = A + (size_t)bm * GK;
    const __half* Bb = B + (size_t)bn * GK;

    const int wm = (wid & 1) * 64;
    const int wn = (wid >> 1) * 64;
    const int r  = lane >> 2;
    const int q  = lane & 3;

    float c[4][8][4];
    gemm_mainloop(sbase, Ab, Bb, t, wm, wn, r, q, c);

#pragma unroll
    for (int i = 0; i < 4; ++i) {
        const int row0 = bm + wm + i * 16 + r;
#pragma unroll
        for (int j = 0; j < 8; ++j) {
            const int col = bn + wn + j * 8 + 2 * q;
            *(float2*)(C + (size_t)row0 * HDIM + col)       = make_float2(c[i][j][0], c[i][j][1]);
            *(float2*)(C + (size_t)(row0 + 8) * HDIM + col) = make_float2(c[i][j][2], c[i][j][3]);
        }
    }
}

// ---------------- attention stage A (fp16 mma) ----------------
__global__ __launch_bounds__(128)
void attn_kvblocks_mma(const float* __restrict__ slope)
{
    const int b = blockIdx.x;
    const int h = blockIdx.y;
    const float s = slope[h];

    __shared__ __half Ks[64][KP2];
    __shared__ __half Vs[64][KP2];

    const int t = threadIdx.x;
    const int w = t >> 5, lane = t & 31;
    const int wm = w * 32;
    const int r = lane >> 2, q = lane & 3;
    const int trow = (lane & 7) + ((lane >> 4) & 1) * 8;
    const int tcol = ((lane >> 3) & 1) * 8;

    const __half* kbase = g_qkvh + (size_t)(b * BLK) * QKVW + h * 384 + 128;
    const __half* vbase = kbase + 128;

    const uint32_t sK = smem_u32(Ks);
    const uint32_t sV = smem_u32(Vs);

    float c[2][16][4];
#pragma unroll
    for (int i = 0; i < 2; ++i)
#pragma unroll
        for (int j = 0; j < 16; ++j)
#pragma unroll
            for (int p = 0; p < 4; ++p) c[i][j][p] = 0.0f;

    for (int ch = 0; ch < 4; ++ch) {
        __syncthreads();
#pragma unroll
        for (int it = 0; it < 8; ++it) {
            int id = t + 128 * it;
            int row = id >> 4;
            int c16 = id & 15;
            int i = ch * 64 + row;
            float kd = expf(-s * (float)(255 - i));
            uint4 k4 = *(const uint4*)(kbase + (size_t)i * QKVW + c16 * 8);
            __half2* hp = (__half2*)&k4;
#pragma unroll
            for (int z = 0; z < 4; ++z) {
                float2 f = __half22float2(hp[z]);
                hp[z] = __floats2half2_rn(f.x * kd, f.y * kd);
            }
            *(uint4*)&Ks[row][c16 * 8] = k4;
            uint4 v4 = *(const uint4*)(vbase + (size_t)i * QKVW + c16 * 8);
            *(uint4*)&Vs[row][c16 * 8] = v4;
        }
        __syncthreads();

#pragma unroll
        for (int kc = 0; kc < 4; ++kc) {
            uint32_t af[2][4], bf[16][2];
#pragma unroll
            for (int i16 = 0; i16 < 2; ++i16) {
                uint32_t addr = sK + ((kc * 16 + trow) * KP2 + wm + i16 * 16 + tcol) * 2;
                ldsm_x4_t(af[i16][0], af[i16][1], af[i16][2], af[i16][3], addr);
            }
#pragma unroll
            for (int jj = 0; jj < 8; ++jj) {
                uint32_t addr = sV + ((kc * 16 + trow) * KP2 + jj * 16 + tcol) * 2;
                ldsm_x4_t(bf[2 * jj][0], bf[2 * jj + 1][0], bf[2 * jj][1], bf[2 * jj + 1][1], addr);
            }
#pragma unroll
            for (int i16 = 0; i16 < 2; ++i16)
#pragma unroll
                for (int j = 0; j < 16; ++j)
                    mma_f16(c[i16][j], af[i16], bf[j]);
        }
    }

    float* Sp = g_S + (size_t)(h * NB + b) * HD * HD;
#pragma unroll
    for (int i16 = 0; i16 < 2; ++i16) {
        const int d0 = wm + i16 * 16 + r;
#pragma unroll
        for (int j = 0; j < 16; ++j) {
            const int e = j * 8 + 2 * q;
            *(float2*)(Sp + (size_t)d0 * HD + e)       = make_float2(c[i16][j][0], c[i16][j][1]);
            *(float2*)(Sp + (size_t)(d0 + 8) * HD + e) = make_float2(c[i16][j][2], c[i16][j][3]);
        }
    }
}

// ---------------- attention stage B (fp32 scan, MLP prefetch, fp16 out) ----------------
__global__ void attn_scan(const float* __restrict__ kv_cache, const float* __restrict__ slope)
{
    const int g = blockIdx.x * 256 + threadIdx.x;
    const int h = g >> 14;
    const int e = g & 16383;
    const float dec = expf(-slope[h] * 256.0f);
    const size_t base = (size_t)h * NB * 16384 + e;

    float sv[NB];
#pragma unroll
    for (int b = 0; b < NB; ++b)
        sv[b] = g_S[base + (size_t)b * 16384];

    float c = kv_cache[(size_t)h * 16384 + e];
#pragma unroll
    for (int b = 0; b < NB; ++b) {
        g_kvsth[base + (size_t)b * 16384] = __float2half_rn(c);
        c = dec * c + sv[b];
    }
}

// ---------------- fused attention output (fp16 hidden store) ----------------
__global__ __launch_bounds__(256, 1)
void attn_out_mma(const float* __restrict__ slope)
{
    extern __shared__ __align__(128) __half osm[];
    const uint32_t sQ = smem_u32(osm);
    const uint32_t sK = sQ + 256 * KP2 * 2;
    const uint32_t sV = sK + 256 * KP2 * 2;
    const uint32_t sP = sV + 256 * KP2 * 2;

    const int b = blockIdx.x;
    const int h = blockIdx.y;
    const float s = slope[h];

    const int t = threadIdx.x;
    const int w = t >> 5, lane = t & 31;
    const int r = lane >> 2, q = lane & 3;
    const int lrow = (lane & 7) + ((lane >> 3) & 1) * 8;
    const int lcol = (lane >> 4) * 8;
    const int trow = (lane & 7) + ((lane >> 4) & 1) * 8;
    const int tcol = ((lane >> 3) & 1) * 8;

    const __half* qkv = g_qkvh + (size_t)(b * BLK) * QKVW + h * 384;
    const __half* kvst = g_kvsth + (size_t)(h * NB + b) * HD * HD;

    __half* Qs = (__half*)osm;
    __half* KVs = Qs + 256 * KP2;

#pragma unroll
    for (int it = 0; it < 16; ++it) {
        int id = t + 256 * it;
        int row = id >> 4, c16 = id & 15;
        *(uint4*)&Qs[row * KP2 + c16 * 8] = *(const uint4*)(qkv + (size_t)row * QKVW + c16 * 8);
    }
#pragma unroll
    for (int it = 0; it < 8; ++it) {
        int id = t + 256 * it;
        int row = id >> 4, c16 = id & 15;
        *(uint4*)&KVs[row * KP2 + c16 * 8] = *(const uint4*)(kvst + (size_t)row * HD + c16 * 8);
    }
    __syncthreads();

    float oc[2][16][4];
#pragma unroll
    for (int tt = 0; tt < 2; ++tt) {
        const int mt = (tt == 0) ? w : (15 - w);
#pragma unroll
        for (int j = 0; j < 16; ++j)
#pragma unroll
            for (int p = 0; p < 4; ++p) oc[tt][j][p] = 0.0f;

#pragma unroll
        for (int kc = 0; kc < 8; ++kc) {
            uint32_t qa[4], bf[16][2];
            ldsm_x4(qa[0], qa[1], qa[2], qa[3],
                    sQ + ((mt * 16 + lrow) * KP2 + kc * 16 + lcol) * 2);
#pragma unroll
            for (int jj = 0; jj < 8; ++jj) {
                ldsm_x4_t(bf[2 * jj][0], bf[2 * jj + 1][0],
                          bf[2 * jj][1], bf[2 * jj + 1][1],
                          sK + ((kc * 16 + trow) * KP2 + jj * 16 + tcol) * 2);
            }
#pragma unroll
            for (int j = 0; j < 16; ++j) mma_f16(oc[tt][j], qa, bf[j]);
        }

        const int mrow = mt * 16 + r;
        const float qd0 = expf(-s * (float)(mrow + 1));
        const float qd8 = expf(-s * (float)(mrow + 9));
#pragma unroll
        for (int j = 0; j < 16; ++j) {
            oc[tt][j][0] *= qd0; oc[tt][j][1] *= qd0;
            oc[tt][j][2] *= qd8; oc[tt][j][3] *= qd8;
        }
    }
    __syncthreads();

    __half* Ks = KVs;
    __half* Vs = Ks + 256 * KP2;
#pragma unroll
    for (int it = 0; it < 16; ++it) {
        int id = t + 256 * it;
        int row = id >> 4, c16 = id & 15;
        *(uint4*)&Ks[row * KP2 + c16 * 8] = *(const uint4*)(qkv + 128 + (size_t)row * QKVW + c16 * 8);
        *(uint4*)&Vs[row * KP2 + c16 * 8] = *(const uint4*)(qkv + 256 + (size_t)row * QKVW + c16 * 8);
    }
    __syncthreads();

    const uint32_t sPw = sP + w * 16 * PSTR * 2;
    __half* Pw = (__half*)(osm) + (sPw - sQ) / 2;

#pragma unroll
    for (int tt = 0; tt < 2; ++tt) {
        const int mt = (tt == 0) ? w : (15 - w);
        const int mrow = mt * 16 + r;

        const int nchunks = mt / 4 + 1;
        for (int nt = 0; nt < nchunks; ++nt) {
            float pc[8][4];
#pragma unroll
            for (int j = 0; j < 8; ++j)
#pragma unroll
                for (int p = 0; p < 4; ++p) pc[j][p] = 0.0f;

#pragma unroll
            for (int kc = 0; kc < 8; ++kc) {
                uint32_t qa[4], kb[8][2];
                ldsm_x4(qa[0], qa[1], qa[2], qa[3],
                        sQ + ((mt * 16 + lrow) * KP2 + kc * 16 + lcol) * 2);
#pragma unroll
                for (int j16 = 0; j16 < 4; ++j16) {
                    ldsm_x4(kb[2 * j16][0], kb[2 * j16 + 1][0],
                            kb[2 * j16][1], kb[2 * j16 + 1][1],
                            sK + ((nt * 64 + j16 * 16 + lrow) * KP2 + kc * 16 + lcol) * 2);
                }
#pragma unroll
                for (int j = 0; j < 8; ++j) mma_f16(pc[j], qa, kb[j]);
            }

#pragma unroll
            for (int j = 0; j < 8; ++j) {
                const int n0 = nt * 64 + j * 8 + 2 * q;
                float f0 = (mrow >= n0)         ? pc[j][0] * expf(-s * (float)(mrow - n0))         : 0.0f;
                float f1 = (mrow >= n0 + 1)     ? pc[j][1] * expf(-s * (float)(mrow - n0 - 1))     : 0.0f;
                float f2 = (mrow + 8 >= n0)     ? pc[j][2] * expf(-s * (float)(mrow + 8 - n0))     : 0.0f;
                float f3 = (mrow + 8 >= n0 + 1) ? pc[j][3] * expf(-s * (float)(mrow + 8 - n0 - 1)) : 0.0f;
                __half2 h0 = __floats2half2_rn(f0, f1);
                __half2 h1 = __floats2half2_rn(f2, f3);
                *(__half2*)&Pw[r * PSTR + j * 8 + 2 * q]       = h0;
                *(__half2*)&Pw[(r + 8) * PSTR + j * 8 + 2 * q] = h1;
            }
            __syncwarp();

#pragma unroll
            for (int ks = 0; ks < 4; ++ks) {
                uint32_t pa[4], vb[16][2];
                ldsm_x4(pa[0], pa[1], pa[2], pa[3],
                        sPw + (lrow * PSTR + ks * 16 + lcol) * 2);
#pragma unroll
                for (int jj = 0; jj < 8; ++jj) {
                    ldsm_x4_t(vb[2 * jj][0], vb[2 * jj + 1][0],
                              vb[2 * jj][1], vb[2 * jj + 1][1],
                              sV + ((nt * 64 + ks * 16 + trow) * KP2 + jj * 16 + tcol) * 2);
                }
#pragma unroll
                for (int j = 0; j < 16; ++j) mma_f16(oc[tt][j], pa, vb[j]);
            }
            __syncwarp();
        }

        __half* hb = g_hiddenh + (size_t)(b * BLK + mt * 16) * INNER + h * HD;
#pragma unroll
        for (int j = 0; j < 16; ++j) {
            const int e = j * 8 + 2 * q;
            __half2 h0 = __floats2half2_rn(oc[tt][j][0], oc[tt][j][1]);
            __half2 h1 = __floats2half2_rn(oc[tt][j][2], oc[tt][j][3]);
            *(__half2*)(hb + (size_t)r * INNER + e)       = h0;
            *(__half2*)(hb + (size_t)(r + 8) * INNER + e) = h1;
        }
    }
}

// ---------------- RMSNorm * weight * gate (fp16 in, smem row cache) -> fp16 ----------------
__global__ __launch_bounds__(256)
void rmsnorm_gate(const float* __restrict__ nw)
{
    __shared__ __half hs[INNER];          // 8KB row cache
    __shared__ float red[256];

    const int m = blockIdx.x;
    const int t = threadIdx.x;
    const __half* hrow = g_hiddenh + (size_t)m * INNER;
    const __half* grow = g_gateh + (size_t)m * INNER;
    __half* orow = g_ghalf + (size_t)m * INNER;

    float ss = 0.0f;
    for (int i = t; i < INNER / 4; i += 256) {
        uint2 h2 = *(const uint2*)(hrow + i * 4);
        *(uint2*)(hs + i * 4) = h2;
        float2 a = __half22float2(*(__half2*)&h2.x);
        float2 bb = __half22float2(*(__half2*)&h2.y);
        ss += a.x * a.x + a.y * a.y + bb.x * bb.x + bb.y * bb.y;
    }
    red[t] = ss;
    __syncthreads();
    for (int s2 = 128; s2 > 0; s2 >>= 1) {
        if (t < s2) red[t] += red[t + s2];
        __syncthreads();
    }
    const float rs = rsqrtf(red[0] / (float)INNER + EPS_RMS);

    for (int i = t; i < INNER / 4; i += 256) {
        uint2 h2 = *(const uint2*)(hs + i * 4);
        float2 a = __half22float2(*(__half2*)&h2.x);
        float2 bb = __half22float2(*(__half2*)&h2.y);
        uint2 g2 = *(const uint2*)(grow + i * 4);
        float2 g0 = __half22float2(*(__half2*)&g2.x);
        float2 g1 = __half22float2(*(__half2*)&g2.y);
        float4 w4 = *(const float4*)(nw + i * 4);
        __half2 o0 = __floats2half2_rn(g0.x * (a.x * rs * w4.x),
                                       g0.y * (a.y * rs * w4.y));
        __half2 o1 = __floats2half2_rn(g1.x * (bb.x * rs * w4.z),
                                       g1.y * (bb.y * rs * w4.w));
        uint2 o;
        o.x = *(uint32_t*)&o0; o.y = *(uint32_t*)&o1;
        *(uint2*)(orow + i * 4) = o;
    }
}

// ---------------- launcher ----------------
extern "C" void kernel_launch(void* const* d_in, const int* in_sizes, int n_in,
                              void* d_out, int out_size)
{
    (void)in_sizes; (void)n_in; (void)out_size;
    const float* x     = (const float*)d_in[0];
    const float* wqkv  = (const float*)d_in[1];
    const float* wgate = (const float*)d_in[2];
    const float* wout  = (const float*)d_in[3];
    const float* nw    = (const float*)d_in[4];
    const float* kvc   = (const float*)d_in[5];
    const float* slope = (const float*)d_in[6];
    float* out = (float*)d_out;

    __half *p_xh = nullptr, *p_wqkvh = nullptr, *p_wgateh = nullptr,
           *p_wouth = nullptr, *p_ghalf = nullptr;
    cudaGetSymbolAddress((void**)&p_xh, g_xh);
    cudaGetSymbolAddress((void**)&p_wqkvh, g_wqkvh);
    cudaGetSymbolAddress((void**)&p_wgateh, g_wgateh);
    cudaGetSymbolAddress((void**)&p_wouth, g_wouth);
    cudaGetSymbolAddress((void**)&p_ghalf, g_ghalf);

    cudaFuncSetAttribute((const void*)gemm_qkvgate, cudaFuncAttributeMaxDynamicSharedMemorySize, GEMM_SMEM);
    cudaFuncSetAttribute((const void*)gemm_out,     cudaFuncAttributeMaxDynamicSharedMemorySize, GEMM_SMEM);
    cudaFuncSetAttribute((const void*)attn_out_mma, cudaFuncAttributeMaxDynamicSharedMemorySize, ATTNOUT_SMEM);

    // all fp32 -> fp16 conversions in one launch (16 floats/thread)
    cvt_all_kernel<<<(M1 + M2 + M3 + M4) / 256, 256>>>(x, wqkv, wgate, wout,
                                                       p_xh, p_wqkvh, p_wgateh, p_wouth);

    // fused: qkv = silu(x@wqkv^T) -> fp16 ; gate = sigmoid(x@wgate^T) -> fp16
    gemm_qkvgate<<<dim3((QKVW + INNER) / BN, SEQ / BM), NTHR, GEMM_SMEM>>>(p_xh, p_wqkvh, p_wgateh);

    // lightning attention
    attn_kvblocks_mma<<<dim3(NB, NH), 128>>>(slope);
    attn_scan<<<(NH * HD * HD) / 256, 256>>>(kvc, slope);
    attn_out_mma<<<dim3(NB, NH), 256, ATTNOUT_SMEM>>>(slope);

    // rmsnorm * weight * gate -> fp16
    rmsnorm_gate<<<SEQ, 256>>>(nw);

    // out = (gate * normed) @ w_out^T
    gemm_out<<<dim3(HDIM / BN, SEQ / BM), NTHR, GEMM_SMEM>>>(p_ghalf, p_wouth, out);
}